// round 4
// baseline (speedup 1.0000x reference)
#include <cuda_runtime.h>
#include <cstdint>

namespace {
constexpr int kB  = 16384;
constexpr int kT  = 79;
constexpr int kH  = 256;
constexpr int kD  = 256;
constexpr int kBM = 128;            // batch rows per CTA
constexpr int kTH = 512;            // threads per CTA (16 warps)
constexpr int kKC = 16;             // k-rows per U chunk
constexpr int kNC = kH / kKC;       // 16 chunks per step

// shared memory layout (bytes)
constexpr int HT_OFF  = 0;                         // hT: [256][128] f32 (transposed h)
constexpr int HT_BY   = kH * kBM * 4;              // 131072
constexpr int UB_OFF  = HT_OFF + HT_BY;            // 2 x duplicated U chunk [16][512]
constexpr int UB_BY   = kKC * 2 * kH * 4;          // 32768
constexpr int WIN_OFF = UB_OFF + 2 * UB_BY;        // duplicated W_in [3][512]
constexpr int BR_OFF  = WIN_OFF + 3 * 2 * kH * 4;  // duplicated b_rnn [512]
constexpr int BD_OFF  = BR_OFF + 2 * kH * 4;       // duplicated b_d   [512]
constexpr int SMEM_BY = BD_OFF + 2 * kH * 4;       // 206848 bytes
}

// ---- packed f32x2 helpers ----
__device__ __forceinline__ void fma2(unsigned long long& c,
                                     unsigned long long a,
                                     unsigned long long b) {
    asm("fma.rn.f32x2 %0, %1, %2, %0;" : "+l"(c) : "l"(a), "l"(b));
}
__device__ __forceinline__ unsigned long long pack2(float lo, float hi) {
    unsigned long long r;
    asm("mov.b64 %0, {%1, %2};" : "=l"(r) : "f"(lo), "f"(hi));
    return r;
}
__device__ __forceinline__ void unpack2(unsigned long long p, float& lo, float& hi) {
    asm("mov.b64 {%0, %1}, %2;" : "=f"(lo), "=f"(hi) : "l"(p));
}
__device__ __forceinline__ void lds2(uint32_t a, unsigned long long& p0, unsigned long long& p1) {
    asm volatile("ld.shared.v2.b64 {%0, %1}, [%2];" : "=l"(p0), "=l"(p1) : "r"(a));
}
__device__ __forceinline__ void sts4(uint32_t a, float v0, float v1, float v2, float v3) {
    asm volatile("st.shared.v4.f32 [%0], {%1, %2, %3, %4};"
                 :: "r"(a), "f"(v0), "f"(v1), "f"(v2), "f"(v3));
}

// Fused reversed-input RNN:
//   hT_sm[k][i] holds h transposed; per step: h = relu(x_t W_in + b_rnn + h U)
//   computed as hT_new[j][i] = relu(proj[j][i] + sum_k U[k][j] * hT[k][i])
// Thread tile: warp w -> j in [16w, 16w+16); lane L -> i in [4L, 4L+4).
// Accumulators are f32x2 pairs along i: A pairs load directly from hT rows,
// B (U row) is stored duplicated in smem so b-pairs load directly too.
__global__ void __launch_bounds__(kTH, 1)
rnn_fused_kernel(const float* __restrict__ x0, const float* __restrict__ x1,
                 const float* __restrict__ x2, const float* __restrict__ Win,
                 const float* __restrict__ U,  const float* __restrict__ brnn,
                 const float* __restrict__ Wd, const float* __restrict__ bd,
                 float* __restrict__ out) {
    extern __shared__ float smemf[];
    const uint32_t sb = (uint32_t)__cvta_generic_to_shared(smemf);

    const int tid = threadIdx.x;
    const int w   = tid >> 5;
    const int L   = tid & 31;
    const int j0  = w * 16;
    const int i0  = L * 4;
    const int b0  = blockIdx.x * kBM;

    // ---- stage duplicated W_in, b_rnn, b_d ----
    for (int idx = tid; idx < 3 * kH; idx += kTH) {
        const int f = idx >> 8, h = idx & 255;
        const float v = Win[f * kH + h];
        smemf[WIN_OFF / 4 + f * 512 + 2 * h]     = v;
        smemf[WIN_OFF / 4 + f * 512 + 2 * h + 1] = v;
    }
    for (int h = tid; h < kH; h += kTH) {
        const float vb = brnn[h];
        smemf[BR_OFF / 4 + 2 * h] = vb; smemf[BR_OFF / 4 + 2 * h + 1] = vb;
        const float vd = bd[h];
        smemf[BD_OFF / 4 + 2 * h] = vd; smemf[BD_OFF / 4 + 2 * h + 1] = vd;
    }
    __syncthreads();

    unsigned long long acc[16][2];
    float2 sreg[4];

    // acc[j][ip] = x0[i]*W_in[0][j] + x1[i]*W_in[1][j] + x2[i]*W_in[2][j] + b_rnn[j]
    auto init_proj = [&](int rt) {
        float a0v[4], a1v[4], a2v[4];
        #pragma unroll
        for (int c = 0; c < 4; c++) {
            const int ofs = (b0 + i0 + c) * kT + rt;
            a0v[c] = __ldg(x0 + ofs);
            a1v[c] = __ldg(x1 + ofs);
            a2v[c] = __ldg(x2 + ofs);
        }
        const unsigned long long xp0[2] = {pack2(a0v[0], a0v[1]), pack2(a0v[2], a0v[3])};
        const unsigned long long xp1[2] = {pack2(a1v[0], a1v[1]), pack2(a1v[2], a1v[3])};
        const unsigned long long xp2[2] = {pack2(a2v[0], a2v[1]), pack2(a2v[2], a2v[3])};
        const uint32_t wb = sb + WIN_OFF + j0 * 8;
        const uint32_t bb = sb + BR_OFF + j0 * 8;
        #pragma unroll
        for (int q = 0; q < 16; q += 2) {
            unsigned long long w0a, w0b, w1a, w1b, w2a, w2b, ba, bbp;
            lds2(bb + q * 8, ba, bbp);
            lds2(wb + q * 8, w0a, w0b);
            lds2(wb + 2048 + q * 8, w1a, w1b);
            lds2(wb + 4096 + q * 8, w2a, w2b);
            #pragma unroll
            for (int ip = 0; ip < 2; ip++) {
                unsigned long long t0 = ba;
                fma2(t0, xp0[ip], w0a); fma2(t0, xp1[ip], w1a); fma2(t0, xp2[ip], w2a);
                acc[q][ip] = t0;
                unsigned long long t1 = bbp;
                fma2(t1, xp0[ip], w0b); fma2(t1, xp1[ip], w1b); fma2(t1, xp2[ip], w2b);
                acc[q + 1][ip] = t1;
            }
        }
    };

    // GEMM over one k-chunk: reads hT rows (broadcast) and duplicated U rows
    auto gemm_chunk = [&](int buf, int c) {
        const uint32_t ab    = sb + HT_OFF + c * kKC * 512 + L * 16;
        const uint32_t bbase = sb + UB_OFF + buf * UB_BY + j0 * 8;
        #pragma unroll
        for (int kk = 0; kk < kKC; kk++) {
            unsigned long long a0, a1, bp[16];
            lds2(ab + kk * 512, a0, a1);
            #pragma unroll
            for (int q = 0; q < 16; q += 2)
                lds2(bbase + kk * 2048 + q * 8, bp[q], bp[q + 1]);
            #pragma unroll
            for (int q = 0; q < 16; q++) {
                fma2(acc[q][0], a0, bp[q]);
                fma2(acc[q][1], a1, bp[q]);
            }
        }
    };

    // stream a 16-row chunk of a [256x256] weight into regs, then dup-store to smem
    auto stage_load = [&](const float* src, int chunk) {
        const float2* s2 = reinterpret_cast<const float2*>(src + chunk * kKC * kH) + w * 128 + L;
        #pragma unroll
        for (int s = 0; s < 4; s++) sreg[s] = __ldg(s2 + 32 * s);
    };
    auto stage_store = [&](int buf) {
        const uint32_t db = sb + UB_OFF + buf * UB_BY + w * 2048 + L * 16;
        #pragma unroll
        for (int s = 0; s < 4; s++)
            sts4(db + s * 512, sreg[s].x, sreg[s].x, sreg[s].y, sreg[s].y);
    };

    auto writeback_relu = [&]() {
        #pragma unroll
        for (int q = 0; q < 16; q++) {
            float v0, v1, v2, v3;
            unpack2(acc[q][0], v0, v1);
            unpack2(acc[q][1], v2, v3);
            v0 = fmaxf(v0, 0.f); v1 = fmaxf(v1, 0.f);
            v2 = fmaxf(v2, 0.f); v3 = fmaxf(v3, 0.f);
            sts4(sb + HT_OFF + (j0 + q) * 512 + L * 16, v0, v1, v2, v3);
        }
    };

    // ---- t = 0: h = relu(proj) ----
    init_proj(kT - 1);
    writeback_relu();
    stage_load(U, 0);
    stage_store(0);
    __syncthreads();

    // ---- t = 1 .. 78 ----
    #pragma unroll 1
    for (int t = 1; t < kT; t++) {
        init_proj(kT - 1 - t);
        #pragma unroll 1
        for (int c = 0; c < kNC; c++) {
            const float* nsrc = (c + 1 < kNC) ? U : ((t + 1 < kT) ? U : Wd);
            stage_load(nsrc, (c + 1) & (kNC - 1));
            gemm_chunk(c & 1, c);
            __syncthreads();
            stage_store((c + 1) & 1);
            __syncthreads();
        }
        writeback_relu();
        __syncthreads();
    }

    // ---- epilogue: out = hT @ W_d + b_d ----
    {
        const uint32_t bb = sb + BD_OFF + j0 * 8;
        #pragma unroll
        for (int q = 0; q < 16; q += 2) {
            unsigned long long p0, p1;
            lds2(bb + q * 8, p0, p1);
            acc[q][0] = p0;     acc[q][1] = p0;
            acc[q + 1][0] = p1; acc[q + 1][1] = p1;
        }
        #pragma unroll 1
        for (int c = 0; c < kNC; c++) {
            if (c + 1 < kNC) stage_load(Wd, c + 1);
            gemm_chunk(c & 1, c);
            if (c + 1 < kNC) {
                __syncthreads();
                stage_store((c + 1) & 1);
                __syncthreads();
            }
        }
        #pragma unroll
        for (int q = 0; q < 16; q++) {
            float v0, v1, v2, v3;
            unpack2(acc[q][0], v0, v1);
            unpack2(acc[q][1], v2, v3);
            float* op = out + (b0 + i0) * kD + (j0 + q);
            op[0]      = v0;
            op[kD]     = v1;
            op[2 * kD] = v2;
            op[3 * kD] = v3;
        }
    }
}

extern "C" void kernel_launch(void* const* d_in, const int* in_sizes, int n_in,
                              void* d_out, int out_size) {
    const float* x0   = (const float*)d_in[0];
    const float* x1   = (const float*)d_in[1];
    const float* x2   = (const float*)d_in[2];
    const float* Win  = (const float*)d_in[3];
    const float* U    = (const float*)d_in[4];
    const float* brnn = (const float*)d_in[5];
    const float* Wd   = (const float*)d_in[6];
    const float* bd   = (const float*)d_in[7];
    float* out = (float*)d_out;

    cudaFuncSetAttribute(rnn_fused_kernel,
                         cudaFuncAttributeMaxDynamicSharedMemorySize, SMEM_BY);
    rnn_fused_kernel<<<kB / kBM, kTH, SMEM_BY>>>(x0, x1, x2, Win, U, brnn, Wd, bd, out);
}

// round 7
// speedup vs baseline: 2.9233x; 2.9233x over previous
#include <cuda_runtime.h>
#include <cuda_bf16.h>
#include <cstdint>

namespace {
constexpr int kT     = 79;
constexpr int kBM    = 128;            // batch rows per CTA
constexpr int kTH    = 512;            // 16 warps: 4(m) x 4(n)
constexpr int NROUND = 79;             // 78 recurrence GEMMs + 1 output GEMM
constexpr int NCHUNK = 8;              // k=32 chunks per 256-K GEMM
constexpr int TOTAL_CH = NROUND * NCHUNK;   // 632
constexpr int PITCH  = 528;            // smem row pitch (512 + 16 pad)

// smem layout (bytes)
constexpr int SM_HHI = 0;                       // h hi  [128][256] bf16, pitch 528
constexpr int HBY    = kBM * PITCH;             // 67584
constexpr int SM_HLO = SM_HHI + HBY;            // h lo
constexpr int SM_UB  = SM_HLO + HBY;            // 2 x (Uhi chunk + Ulo chunk)
constexpr int UCH_BY = 32 * PITCH;              // 16896 per hi/lo chunk
constexpr int UBUF_BY = 2 * UCH_BY;             // 33792 per buffer
constexpr int SM_WT  = SM_UB + 2 * UBUF_BY;     // float4[256] = (W0,W1,W2,b_rnn)
constexpr int SM_BD  = SM_WT + 4096;            // float[256] b_d
constexpr int SMEM_BYTES = SM_BD + 1024;        // 207872
}

// Pre-split B operands (row-major [k][n] = U layout as-is), bf16 hi/lo.
__device__ __align__(16) unsigned char g_Uh[131072];
__device__ __align__(16) unsigned char g_Ul[131072];
__device__ __align__(16) unsigned char g_Wh[131072];
__device__ __align__(16) unsigned char g_Wl[131072];

// ---------------- PTX helpers ----------------
__device__ __forceinline__ void ldsm4(uint32_t (&r)[4], uint32_t a) {
    asm volatile("ldmatrix.sync.aligned.m8n8.x4.shared.b16 {%0,%1,%2,%3}, [%4];"
                 : "=r"(r[0]), "=r"(r[1]), "=r"(r[2]), "=r"(r[3]) : "r"(a));
}
__device__ __forceinline__ void ldsm4t(uint32_t (&r)[4], uint32_t a) {
    asm volatile("ldmatrix.sync.aligned.m8n8.x4.trans.shared.b16 {%0,%1,%2,%3}, [%4];"
                 : "=r"(r[0]), "=r"(r[1]), "=r"(r[2]), "=r"(r[3]) : "r"(a));
}
__device__ __forceinline__ void mma16816(float (&d)[4], const uint32_t (&a)[4],
                                         uint32_t b0, uint32_t b1) {
    asm volatile(
        "mma.sync.aligned.m16n8k16.row.col.f32.bf16.bf16.f32 "
        "{%0,%1,%2,%3}, {%4,%5,%6,%7}, {%8,%9}, {%0,%1,%2,%3};"
        : "+f"(d[0]), "+f"(d[1]), "+f"(d[2]), "+f"(d[3])
        : "r"(a[0]), "r"(a[1]), "r"(a[2]), "r"(a[3]), "r"(b0), "r"(b1));
}
__device__ __forceinline__ void cpa16(uint32_t d, const void* s) {
    asm volatile("cp.async.cg.shared.global [%0], [%1], 16;" :: "r"(d), "l"(s));
}
__device__ __forceinline__ void cp_commit() {
    asm volatile("cp.async.commit_group;" ::: "memory");
}
__device__ __forceinline__ void st32s(uint32_t a, uint32_t v) {
    asm volatile("st.shared.b32 [%0], %1;" :: "r"(a), "r"(v));
}
// pack: low 16 = bf16(v0), high 16 = bf16(v1)
__device__ __forceinline__ uint32_t cvt_pack(float v0, float v1) {
    uint32_t r;
    asm("cvt.rn.bf16x2.f32 %0, %1, %2;" : "=r"(r) : "f"(v1), "f"(v0));
    return r;
}

// ---------------- prep: split U / Wd into bf16 hi/lo blobs ----------------
__global__ void prep_kernel(const float* __restrict__ U, const float* __restrict__ Wd) {
    const int idx = blockIdx.x * 256 + threadIdx.x;         // 65536 elems
    {
        const float v = U[idx];
        const __nv_bfloat16 h = __float2bfloat16(v);
        ((__nv_bfloat16*)g_Uh)[idx] = h;
        ((__nv_bfloat16*)g_Ul)[idx] = __float2bfloat16(v - __bfloat162float(h));
    }
    {
        const float v = Wd[idx];
        const __nv_bfloat16 h = __float2bfloat16(v);
        ((__nv_bfloat16*)g_Wh)[idx] = h;
        ((__nv_bfloat16*)g_Wl)[idx] = __float2bfloat16(v - __bfloat162float(h));
    }
}

// ---------------- main fused RNN kernel (HMMA) ----------------
__global__ void __launch_bounds__(kTH, 1)
rnn_hmma_kernel(const float* __restrict__ x0, const float* __restrict__ x1,
                const float* __restrict__ x2, const float* __restrict__ Win,
                const float* __restrict__ brnn, const float* __restrict__ bd,
                float* __restrict__ out) {
    extern __shared__ unsigned char smem[];
    const uint32_t sb = (uint32_t)__cvta_generic_to_shared(smem);

    const int tid = threadIdx.x;
    const int w   = tid >> 5;
    const int L   = tid & 31;
    const int wm  = w & 3;                 // warp m-tile (32 rows)
    const int wn  = w >> 2;                // warp n-tile (64 cols)
    const int gid = L >> 2;                // fragment row group
    const int tig = L & 3;                 // fragment col pair
    const int b0  = blockIdx.x * kBM;

    // stage proj table (W0,W1,W2,b_rnn per col) + b_d
    if (tid < 256) {
        float4 wv = make_float4(Win[tid], Win[256 + tid], Win[512 + tid], brnn[tid]);
        *reinterpret_cast<float4*>(smem + SM_WT + tid * 16) = wv;
        *reinterpret_cast<float*>(smem + SM_BD + tid * 4) = bd[tid];
    }

    // lane-invariant smem offsets for ldmatrix
    const uint32_t aBase = sb + SM_HHI +
        (uint32_t)((wm * 32 + (L & 15)) * PITCH + (L >> 4) * 16);
    const uint32_t bOff =
        (uint32_t)((L & 15) * PITCH + (L >> 4) * 16 + wn * 128);

    // stream one k=32 chunk (hi+lo) of B into buffer (gi&1)
    auto issue_chunk = [&](int gi) {
        const bool lastR = gi >= (NROUND - 1) * NCHUNK;
        const unsigned char* sH = lastR ? g_Wh : g_Uh;
        const unsigned char* sL = lastR ? g_Wl : g_Ul;
        const int cc = gi & 7;
        const uint32_t dst = sb + SM_UB + (uint32_t)(gi & 1) * UBUF_BY;
        #pragma unroll
        for (int i = 0; i < 4; i++) {
            const int u   = tid + kTH * i;          // 0..2047 16B units
            const int hi  = (u < 1024);
            const int uu  = u & 1023;
            const int row = uu >> 5;
            const int off = (uu & 31) * 16;
            const unsigned char* s = (hi ? sH : sL) + (cc * 32 + row) * 512 + off;
            const uint32_t d = dst + (hi ? 0u : (uint32_t)UCH_BY)
                                   + (uint32_t)(row * PITCH + off);
            cpa16(d, s);
        }
        cp_commit();
    };

    float acc[2][8][4];

    // epilogue: h = relu(proj(col) [+ D]); split to bf16 hi/lo in smem
    auto epilogue = [&](int col, bool addD) {
        float xs0[4], xs1[4], xs2[4];
        #pragma unroll
        for (int q = 0; q < 4; q++) {
            const int row = wm * 32 + (q >> 1) * 16 + (q & 1) * 8 + gid;
            const int idx = (b0 + row) * kT + col;
            xs0[q] = __ldg(x0 + idx);
            xs1[q] = __ldg(x1 + idx);
            xs2[q] = __ldg(x2 + idx);
        }
        #pragma unroll
        for (int nt = 0; nt < 8; nt++) {
            const int cb = wn * 64 + nt * 8 + 2 * tig;
            const float4 wA = *reinterpret_cast<const float4*>(smem + SM_WT + cb * 16);
            const float4 wB = *reinterpret_cast<const float4*>(smem + SM_WT + cb * 16 + 16);
            #pragma unroll
            for (int mt = 0; mt < 2; mt++)
            #pragma unroll
            for (int hf = 0; hf < 2; hf++) {
                const int q = mt * 2 + hf;
                float v0 = wA.w + xs0[q] * wA.x + xs1[q] * wA.y + xs2[q] * wA.z;
                float v1 = wB.w + xs0[q] * wB.x + xs1[q] * wB.y + xs2[q] * wB.z;
                if (addD) {
                    v0 += acc[mt][nt][hf * 2];
                    v1 += acc[mt][nt][hf * 2 + 1];
                }
                v0 = fmaxf(v0, 0.f);
                v1 = fmaxf(v1, 0.f);
                const uint32_t hp = cvt_pack(v0, v1);
                const float h0 = __uint_as_float(hp << 16);
                const float h1 = __uint_as_float(hp & 0xFFFF0000u);
                const uint32_t lp = cvt_pack(v0 - h0, v1 - h1);
                const int row = wm * 32 + mt * 16 + hf * 8 + gid;
                const uint32_t ad = sb + SM_HHI + (uint32_t)(row * PITCH + cb * 2);
                st32s(ad, hp);
                st32s(ad + HBY, lp);
            }
        }
    };

    // prologue: first two chunks in flight
    issue_chunk(0);
    issue_chunk(1);
    __syncthreads();                       // proj table visible

    // h1 = relu(proj(col 78))  (h0 = 0)
    epilogue(kT - 1, false);

    #pragma unroll 1
    for (int r = 0; r < NROUND; r++) {
        #pragma unroll
        for (int mt = 0; mt < 2; mt++)
            #pragma unroll
            for (int nt = 0; nt < 8; nt++)
                #pragma unroll
                for (int e = 0; e < 4; e++) acc[mt][nt][e] = 0.f;

        #pragma unroll 2
        for (int c = 0; c < NCHUNK; c++) {
            const int gi = r * NCHUNK + c;
            if (gi + 2 < TOTAL_CH)
                asm volatile("cp.async.wait_group 1;" ::: "memory");
            else
                asm volatile("cp.async.wait_group 0;" ::: "memory");
            __syncthreads();               // chunk gi ready; h writes visible

            const uint32_t ub = sb + SM_UB + (uint32_t)(gi & 1) * UBUF_BY;
            #pragma unroll
            for (int kh = 0; kh < 2; kh++) {
                const uint32_t ka = (uint32_t)(c * 64 + kh * 32);  // A k-offset bytes
                uint32_t ahi[2][4], alo[2][4];
                ldsm4(ahi[0], aBase + ka);
                ldsm4(ahi[1], aBase + 8448 + ka);                  // +16 rows
                ldsm4(alo[0], aBase + HBY + ka);
                ldsm4(alo[1], aBase + HBY + 8448 + ka);
                #pragma unroll
                for (int g = 0; g < 4; g++) {
                    uint32_t bh[4], bl[4];
                    const uint32_t bb = ub + bOff + (uint32_t)(kh * 16 * PITCH + g * 32);
                    ldsm4t(bh, bb);
                    ldsm4t(bl, bb + UCH_BY);
                    #pragma unroll
                    for (int mt = 0; mt < 2; mt++) {
                        mma16816(acc[mt][2 * g],     ahi[mt], bh[0], bh[1]);
                        mma16816(acc[mt][2 * g],     alo[mt], bh[0], bh[1]);
                        mma16816(acc[mt][2 * g],     ahi[mt], bl[0], bl[1]);
                        mma16816(acc[mt][2 * g + 1], ahi[mt], bh[2], bh[3]);
                        mma16816(acc[mt][2 * g + 1], alo[mt], bh[2], bh[3]);
                        mma16816(acc[mt][2 * g + 1], ahi[mt], bl[2], bl[3]);
                    }
                }
            }
            __syncthreads();               // all reads of buffer done
            if (gi + 2 < TOTAL_CH) issue_chunk(gi + 2);
        }

        if (r < NROUND - 1) {
            epilogue(kT - 2 - r, true);    // cols 77..0
        } else {
            // out = D + b_d
            #pragma unroll
            for (int nt = 0; nt < 8; nt++) {
                const int cb = wn * 64 + nt * 8 + 2 * tig;
                const float bd0 = *reinterpret_cast<const float*>(smem + SM_BD + cb * 4);
                const float bd1 = *reinterpret_cast<const float*>(smem + SM_BD + cb * 4 + 4);
                #pragma unroll
                for (int mt = 0; mt < 2; mt++)
                #pragma unroll
                for (int hf = 0; hf < 2; hf++) {
                    const int row = wm * 32 + mt * 16 + hf * 8 + gid;
                    float2 o;
                    o.x = acc[mt][nt][hf * 2]     + bd0;
                    o.y = acc[mt][nt][hf * 2 + 1] + bd1;
                    *reinterpret_cast<float2*>(out + (size_t)(b0 + row) * 256 + cb) = o;
                }
            }
        }
    }
}

extern "C" void kernel_launch(void* const* d_in, const int* in_sizes, int n_in,
                              void* d_out, int out_size) {
    const float* x0   = (const float*)d_in[0];
    const float* x1   = (const float*)d_in[1];
    const float* x2   = (const float*)d_in[2];
    const float* Win  = (const float*)d_in[3];
    const float* U    = (const float*)d_in[4];
    const float* brnn = (const float*)d_in[5];
    const float* Wd   = (const float*)d_in[6];
    const float* bd   = (const float*)d_in[7];
    float* out = (float*)d_out;

    prep_kernel<<<256, 256>>>(U, Wd);

    cudaFuncSetAttribute(rnn_hmma_kernel,
                         cudaFuncAttributeMaxDynamicSharedMemorySize, SMEM_BYTES);
    rnn_hmma_kernel<<<16384 / kBM, kTH, SMEM_BYTES>>>(x0, x1, x2, Win, brnn, bd, out);
}

// round 8
// speedup vs baseline: 3.5164x; 1.2029x over previous
#include <cuda_runtime.h>
#include <cuda_bf16.h>
#include <cstdint>

namespace {
constexpr int kT     = 79;
constexpr int kBM    = 128;            // batch rows per CTA
constexpr int kTH    = 512;            // 16 warps: wm = w&3 (rows), wn = w>>2 (cols)
constexpr int NROUND = 79;             // 78 recurrence GEMMs + 1 output GEMM
constexpr int NCHUNK = 8;              // k=32 chunks per 256-K GEMM
constexpr int TOTAL_CH = NROUND * NCHUNK;   // 632

// smem layout (bytes) — all tiles XOR-swizzled, no padding
constexpr int SM_HHI = 0;                       // h hi [128][512B]
constexpr int SM_HLO = 65536;                   // h lo [128][512B]
constexpr int SM_B   = 131072;                  // 4 quads x 2 stages x 8KB
constexpr int SM_WT  = 131072 + 65536;          // float4[256] = (W0,W1,W2,b_rnn)
constexpr int SMEM_BYTES = SM_WT + 4096;        // 200704
}

// Pre-split B operands (row-major [k][n] like U), bf16 hi/lo.
__device__ __align__(16) unsigned char g_Uh[131072];
__device__ __align__(16) unsigned char g_Ul[131072];
__device__ __align__(16) unsigned char g_Wh[131072];
__device__ __align__(16) unsigned char g_Wl[131072];

// ---------------- PTX helpers ----------------
__device__ __forceinline__ void ldsm4(uint32_t (&r)[4], uint32_t a) {
    asm volatile("ldmatrix.sync.aligned.m8n8.x4.shared.b16 {%0,%1,%2,%3}, [%4];"
                 : "=r"(r[0]), "=r"(r[1]), "=r"(r[2]), "=r"(r[3]) : "r"(a));
}
__device__ __forceinline__ void ldsm4t(uint32_t (&r)[4], uint32_t a) {
    asm volatile("ldmatrix.sync.aligned.m8n8.x4.trans.shared.b16 {%0,%1,%2,%3}, [%4];"
                 : "=r"(r[0]), "=r"(r[1]), "=r"(r[2]), "=r"(r[3]) : "r"(a));
}
__device__ __forceinline__ void mma16816(float (&d)[4], const uint32_t (&a)[4],
                                         uint32_t b0, uint32_t b1) {
    asm volatile(
        "mma.sync.aligned.m16n8k16.row.col.f32.bf16.bf16.f32 "
        "{%0,%1,%2,%3}, {%4,%5,%6,%7}, {%8,%9}, {%0,%1,%2,%3};"
        : "+f"(d[0]), "+f"(d[1]), "+f"(d[2]), "+f"(d[3])
        : "r"(a[0]), "r"(a[1]), "r"(a[2]), "r"(a[3]), "r"(b0), "r"(b1));
}
__device__ __forceinline__ void cpa16(uint32_t d, const void* s) {
    asm volatile("cp.async.cg.shared.global [%0], [%1], 16;" :: "r"(d), "l"(s));
}
__device__ __forceinline__ void cp_commit() {
    asm volatile("cp.async.commit_group;" ::: "memory");
}
__device__ __forceinline__ void st32s(uint32_t a, uint32_t v) {
    asm volatile("st.shared.b32 [%0], %1;" :: "r"(a), "r"(v));
}
__device__ __forceinline__ void barx(int id) {
    asm volatile("bar.sync %0, 128;" :: "r"(id) : "memory");
}
// pack: low 16 = bf16(v0), high 16 = bf16(v1)
__device__ __forceinline__ uint32_t cvt_pack(float v0, float v1) {
    uint32_t r;
    asm("cvt.rn.bf16x2.f32 %0, %1, %2;" : "=r"(r) : "f"(v1), "f"(v0));
    return r;
}

// ---------------- prep: split U / Wd into bf16 hi/lo blobs ----------------
__global__ void prep_kernel(const float* __restrict__ U, const float* __restrict__ Wd) {
    const int idx = blockIdx.x * 256 + threadIdx.x;         // 65536 elems
    {
        const float v = U[idx];
        const __nv_bfloat16 h = __float2bfloat16(v);
        ((__nv_bfloat16*)g_Uh)[idx] = h;
        ((__nv_bfloat16*)g_Ul)[idx] = __float2bfloat16(v - __bfloat162float(h));
    }
    {
        const float v = Wd[idx];
        const __nv_bfloat16 h = __float2bfloat16(v);
        ((__nv_bfloat16*)g_Wh)[idx] = h;
        ((__nv_bfloat16*)g_Wl)[idx] = __float2bfloat16(v - __bfloat162float(h));
    }
}

// ---------------- main fused RNN kernel (HMMA, quad-local sync) ----------------
__global__ void __launch_bounds__(kTH, 1)
rnn_hmma_kernel(const float* __restrict__ x0, const float* __restrict__ x1,
                const float* __restrict__ x2, const float* __restrict__ Win,
                const float* __restrict__ brnn, const float* __restrict__ bd,
                float* __restrict__ out) {
    extern __shared__ unsigned char smem[];
    const uint32_t sb = (uint32_t)__cvta_generic_to_shared(smem);

    const int tid = threadIdx.x;
    const int w   = tid >> 5;
    const int L   = tid & 31;
    const int wm  = w & 3;                 // row-group (32 m-rows)
    const int wn  = w >> 2;                // quad (64 n-cols); quad tids contiguous
    const int gid = L >> 2;
    const int tig = L & 3;
    const int b0  = blockIdx.x * kBM;

    // stage proj table (W0,W1,W2,b_rnn per col)
    if (tid < 256) {
        float4 wv = make_float4(Win[tid], Win[256 + tid], Win[512 + tid], brnn[tid]);
        *reinterpret_cast<float4*>(smem + SM_WT + tid * 16) = wv;
    }

    // lane-invariant pieces for swizzled ldmatrix addressing
    const int arow   = wm * 32 + (L & 15);                 // A row (first 16-row tile)
    const uint32_t axor  = (uint32_t)((arow & 7) << 4);
    const uint32_t aseg  = (uint32_t)((L >> 4) * 16);
    const uint32_t aHi   = sb + SM_HHI + (uint32_t)arow * 512;
    const uint32_t aLo   = sb + SM_HLO + (uint32_t)arow * 512;
    const int brow   = L & 15;                             // B k-row within 16
    const uint32_t bxor  = (uint32_t)((brow & 7) << 4);
    const uint32_t bseg  = (uint32_t)((L >> 4) * 16);
    const uint32_t bRow  = (uint32_t)brow * 128;

    // quad-private B stream: one k=32 chunk slice (hi 4KB + lo 4KB)
    auto issue_chunk = [&](int gi) {
        const bool lastR = gi >= (NROUND - 1) * NCHUNK;
        const unsigned char* sH = lastR ? g_Wh : g_Uh;
        const unsigned char* sL = lastR ? g_Wl : g_Ul;
        const int cc = gi & 7;
        const uint32_t dst = sb + SM_B + (uint32_t)wn * 16384u + (uint32_t)(gi & 1) * 8192u;
        const int lt = tid & 127;
        #pragma unroll
        for (int i = 0; i < 4; i++) {
            const int u   = lt + 128 * i;           // 0..511 16B units
            const int hi  = (u < 256);
            const int uu  = u & 255;
            const int row = uu >> 3;                // 0..31
            const int seg = (uu & 7) * 16;          // 0..112
            const unsigned char* s =
                (hi ? sH : sL) + (cc * 32 + row) * 512 + wn * 128 + seg;
            const uint32_t d = dst + (hi ? 0u : 4096u)
                             + (uint32_t)(row * 128 + (seg ^ ((row & 7) << 4)));
            cpa16(d, s);
        }
        cp_commit();
    };

    float acc[2][8][4];

    auto do_chunk = [&](int c, uint32_t qb) {
        #pragma unroll
        for (int kh = 0; kh < 2; kh++) {
            const uint32_t koff = (uint32_t)(c * 64 + kh * 32);
            const uint32_t ak = (koff + aseg) ^ axor;
            uint32_t ahi[2][4], alo[2][4];
            ldsm4(ahi[0], aHi + ak);
            ldsm4(ahi[1], aHi + 8192 + ak);
            ldsm4(alo[0], aLo + ak);
            ldsm4(alo[1], aLo + 8192 + ak);
            #pragma unroll
            for (int g = 0; g < 4; g++) {
                uint32_t bh[4], bl[4];
                const uint32_t ba = qb + (uint32_t)kh * 2048 + bRow
                                  + (((uint32_t)(g * 32) + bseg) ^ bxor);
                ldsm4t(bh, ba);
                ldsm4t(bl, ba + 4096);
                // term-major: same-accumulator chain distance = 4
                mma16816(acc[0][2 * g],     ahi[0], bh[0], bh[1]);
                mma16816(acc[1][2 * g],     ahi[1], bh[0], bh[1]);
                mma16816(acc[0][2 * g + 1], ahi[0], bh[2], bh[3]);
                mma16816(acc[1][2 * g + 1], ahi[1], bh[2], bh[3]);
                mma16816(acc[0][2 * g],     alo[0], bh[0], bh[1]);
                mma16816(acc[1][2 * g],     alo[1], bh[0], bh[1]);
                mma16816(acc[0][2 * g + 1], alo[0], bh[2], bh[3]);
                mma16816(acc[1][2 * g + 1], alo[1], bh[2], bh[3]);
                mma16816(acc[0][2 * g],     ahi[0], bl[0], bl[1]);
                mma16816(acc[1][2 * g],     ahi[1], bl[0], bl[1]);
                mma16816(acc[0][2 * g + 1], ahi[0], bl[2], bl[3]);
                mma16816(acc[1][2 * g + 1], ahi[1], bl[2], bl[3]);
            }
        }
    };

    // epilogue: h = relu(proj(col) [+ D]); split to bf16 hi/lo in swizzled smem
    float xs0[4], xs1[4], xs2[4];
    auto load_xs = [&](int col) {
        #pragma unroll
        for (int q = 0; q < 4; q++) {
            const int row = wm * 32 + (q >> 1) * 16 + (q & 1) * 8 + gid;
            const int idx = (b0 + row) * kT + col;
            xs0[q] = __ldg(x0 + idx);
            xs1[q] = __ldg(x1 + idx);
            xs2[q] = __ldg(x2 + idx);
        }
    };
    auto epilogue = [&](bool addD) {
        #pragma unroll
        for (int nt = 0; nt < 8; nt++) {
            const int cb = wn * 64 + nt * 8 + 2 * tig;
            const float4 wA = *reinterpret_cast<const float4*>(smem + SM_WT + cb * 16);
            const float4 wB = *reinterpret_cast<const float4*>(smem + SM_WT + cb * 16 + 16);
            #pragma unroll
            for (int mt = 0; mt < 2; mt++)
            #pragma unroll
            for (int hf = 0; hf < 2; hf++) {
                const int q = mt * 2 + hf;
                float v0 = wA.w + xs0[q] * wA.x + xs1[q] * wA.y + xs2[q] * wA.z;
                float v1 = wB.w + xs0[q] * wB.x + xs1[q] * wB.y + xs2[q] * wB.z;
                if (addD) {
                    v0 += acc[mt][nt][hf * 2];
                    v1 += acc[mt][nt][hf * 2 + 1];
                }
                v0 = fmaxf(v0, 0.f);
                v1 = fmaxf(v1, 0.f);
                const uint32_t hp = cvt_pack(v0, v1);
                const float h0 = __uint_as_float(hp << 16);
                const float h1 = __uint_as_float(hp & 0xFFFF0000u);
                const uint32_t lp = cvt_pack(v0 - h0, v1 - h1);
                const int row = wm * 32 + mt * 16 + hf * 8 + gid;
                const uint32_t off =
                    (uint32_t)(row * 512 + ((cb * 2) ^ ((row & 7) << 4)));
                st32s(sb + SM_HHI + off, hp);
                st32s(sb + SM_HLO + off, lp);
            }
        }
    };

    // ---- prologue ----
    issue_chunk(0);
    issue_chunk(1);
    __syncthreads();                       // proj table visible
    load_xs(kT - 1);
    epilogue(false);                       // h1 = relu(proj(col 78)), h0 = 0
    barx(5 + wm);                          // h rows wm visible to row-group

    // ---- rounds ----
    #pragma unroll 1
    for (int r = 0; r < NROUND; r++) {
        if (r < NROUND - 1) load_xs(kT - 2 - r);
        #pragma unroll
        for (int mt = 0; mt < 2; mt++)
            #pragma unroll
            for (int nt = 0; nt < 8; nt++)
                #pragma unroll
                for (int e = 0; e < 4; e++) acc[mt][nt][e] = 0.f;

        #pragma unroll 2
        for (int c = 0; c < NCHUNK; c++) {
            const int gi = r * NCHUNK + c;
            if (gi + 2 < TOTAL_CH)
                asm volatile("cp.async.wait_group 1;" ::: "memory");
            else
                asm volatile("cp.async.wait_group 0;" ::: "memory");
            barx(1 + wn);                  // quad: stage (gi&1) ready everywhere
            const uint32_t qb =
                sb + SM_B + (uint32_t)wn * 16384u + (uint32_t)(gi & 1) * 8192u;
            do_chunk(c, qb);
            barx(1 + wn);                  // quad: all reads of stage done
            if (gi + 2 < TOTAL_CH) issue_chunk(gi + 2);
        }

        barx(5 + wm);                      // row-group: A reads of rows wm done
        if (r < NROUND - 1) {
            epilogue(true);                // h_{t+1}
            barx(5 + wm);                  // h rows wm written
        } else {
            // out = D + b_d
            #pragma unroll
            for (int nt = 0; nt < 8; nt++) {
                const int cb = wn * 64 + nt * 8 + 2 * tig;
                const float bd0 = __ldg(bd + cb);
                const float bd1 = __ldg(bd + cb + 1);
                #pragma unroll
                for (int mt = 0; mt < 2; mt++)
                #pragma unroll
                for (int hf = 0; hf < 2; hf++) {
                    const int row = wm * 32 + mt * 16 + hf * 8 + gid;
                    float2 o;
                    o.x = acc[mt][nt][hf * 2]     + bd0;
                    o.y = acc[mt][nt][hf * 2 + 1] + bd1;
                    *reinterpret_cast<float2*>(out + (size_t)(b0 + row) * 256 + cb) = o;
                }
            }
        }
    }
}

extern "C" void kernel_launch(void* const* d_in, const int* in_sizes, int n_in,
                              void* d_out, int out_size) {
    const float* x0   = (const float*)d_in[0];
    const float* x1   = (const float*)d_in[1];
    const float* x2   = (const float*)d_in[2];
    const float* Win  = (const float*)d_in[3];
    const float* U    = (const float*)d_in[4];
    const float* brnn = (const float*)d_in[5];
    const float* Wd   = (const float*)d_in[6];
    const float* bd   = (const float*)d_in[7];
    float* out = (float*)d_out;

    prep_kernel<<<256, 256>>>(U, Wd);

    cudaFuncSetAttribute(rnn_hmma_kernel,
                         cudaFuncAttributeMaxDynamicSharedMemorySize, SMEM_BYTES);
    rnn_hmma_kernel<<<16384 / kBM, kTH, SMEM_BYTES>>>(x0, x1, x2, Win, brnn, bd, out);
}